// round 10
// baseline (speedup 1.0000x reference)
#include <cuda_runtime.h>

#define NA 8192
#define NN 65536
#define NE 262144
#define DD 128
#define GN_EPS 1e-5f
#define TILE 64
#define STR 132      // activation row stride (floats)
#define NTH 256
#define WCH 16       // weight k-chunk width
#define SWBUF (WCH * 128)

// scratch (device globals: allocation-free rule)
__device__ __align__(16) float g_qc[NA * DD];      // q @ ctx0_Wq^T  per actor
__device__ __align__(16) float g_nc[NN * DD];      // nodes @ ctx0_Wc^T per node
__device__ __align__(16) float g_a[NA * DD];       // agt accumulator
__device__ __align__(16) float g_actors[NA * DD];  // inter-block actors

// ---------- packed f32x2 helpers ----------
__device__ __forceinline__ void ffma2(unsigned long long& acc, unsigned long long w,
                                      unsigned long long a) {
    asm volatile("fma.rn.f32x2 %0, %1, %2, %0;" : "+l"(acc) : "l"(w), "l"(a));
}
__device__ __forceinline__ unsigned long long pack2(float x) {
    unsigned long long r;
    asm("mov.b64 %0, {%1, %1};" : "=l"(r) : "f"(x));
    return r;
}
__device__ __forceinline__ unsigned long long packf2(float lo, float hi) {
    unsigned long long r;
    asm("mov.b64 %0, {%1, %2};" : "=l"(r) : "f"(lo), "f"(hi));
    return r;
}
__device__ __forceinline__ float2 unpack2(unsigned long long v) {
    float2 r;
    asm("mov.b64 {%0, %1}, %2;" : "=f"(r.x), "=f"(r.y) : "l"(v));
    return r;
}
__device__ __forceinline__ void redv4(const float* p, float a, float b, float c, float d) {
    asm volatile("red.global.add.v4.f32 [%0], {%1, %2, %3, %4};"
                 :: "l"(p), "f"(a), "f"(b), "f"(c), "f"(d) : "memory");
}

// thread tile geometry: 8 warps = 4 edge-blocks x 2 oc-blocks
// thread owns edges [eRow0, eRow0+4), ocs [o0, o0+8)
struct TG {
    int t, lane, og, ocblk, eRow0, o0;
};
__device__ __forceinline__ TG tgeom() {
    TG g;
    g.t = threadIdx.x;
    const int warp = g.t >> 5;
    g.lane = g.t & 31;
    g.og = g.lane & 7;
    g.ocblk = warp & 1;
    g.eRow0 = (warp >> 1) * 16 + (g.lane >> 3) * 4;
    g.o0 = g.ocblk * 64 + g.og * 8;
    return g;
}

// ---------- 4x8 register-tile GEMM: acc += Act[64][K=128] * W[128][K]^T ----------
__device__ __forceinline__ void gemm4x8(const float* __restrict__ W, int ldW,
                                        const float* sAct, float* sW,
                                        unsigned long long (&acc)[4][4], const TG& g) {
    const int oc = g.t & 127;
    const int kh = (g.t >> 7) * 8;
    const int nch = DD >> 4;
    float4 w0 = *(const float4*)(W + oc * ldW + kh);
    float4 w1 = *(const float4*)(W + oc * ldW + kh + 4);
    for (int c = 0; c < nch; c++) {
        float* sb = sW + (c & 1) * SWBUF;
        sb[(kh + 0) * 128 + oc] = w0.x;
        sb[(kh + 1) * 128 + oc] = w0.y;
        sb[(kh + 2) * 128 + oc] = w0.z;
        sb[(kh + 3) * 128 + oc] = w0.w;
        sb[(kh + 4) * 128 + oc] = w1.x;
        sb[(kh + 5) * 128 + oc] = w1.y;
        sb[(kh + 6) * 128 + oc] = w1.z;
        sb[(kh + 7) * 128 + oc] = w1.w;
        __syncthreads();
        if (c + 1 < nch) {
            const float* Wp = W + oc * ldW + ((c + 1) << 4) + kh;
            w0 = *(const float4*)(Wp);
            w1 = *(const float4*)(Wp + 4);
        }
        const int k0 = c << 4;
#pragma unroll
        for (int kq = 0; kq < 4; kq++) {
            float4 a4[4];
#pragma unroll
            for (int i = 0; i < 4; i++)
                a4[i] = *(const float4*)(sAct + (g.eRow0 + i) * STR + k0 + kq * 4);
#pragma unroll
            for (int kk = 0; kk < 4; kk++) {
                const int k = kq * 4 + kk;
                const ulonglong2 wa = *(const ulonglong2*)(sb + k * 128 + g.o0);
                const ulonglong2 wb = *(const ulonglong2*)(sb + k * 128 + g.o0 + 4);
#pragma unroll
                for (int i = 0; i < 4; i++) {
                    const float av = (kk == 0) ? a4[i].x : (kk == 1) ? a4[i].y
                                   : (kk == 2) ? a4[i].z : a4[i].w;
                    const unsigned long long aa = pack2(av);
                    ffma2(acc[i][0], wa.x, aa);
                    ffma2(acc[i][1], wa.y, aa);
                    ffma2(acc[i][2], wb.x, aa);
                    ffma2(acc[i][3], wb.y, aa);
                }
            }
        }
    }
}

// ---------- GroupNorm(1 group, 128 ch) from accumulator registers ----------
// MODE 1: store relu(y)    MODE 2: store relu(y + res)
template <int MODE>
__device__ __forceinline__ void gn_regs(const unsigned long long (&acc)[4][4],
                                        float* dst, int dstStride,
                                        const float* __restrict__ gamma,
                                        const float* __restrict__ beta,
                                        float* sRed, const TG& g, const float* res) {
    const float4 g0 = *(const float4*)(gamma + g.o0);
    const float4 g1 = *(const float4*)(gamma + g.o0 + 4);
    const float4 b0 = *(const float4*)(beta + g.o0);
    const float4 b1 = *(const float4*)(beta + g.o0 + 4);
#pragma unroll
    for (int i = 0; i < 4; i++) {
        float s = 0.f, s2 = 0.f;
#pragma unroll
        for (int j = 0; j < 4; j++) {
            float2 p = unpack2(acc[i][j]);
            s += p.x + p.y;
            s2 += p.x * p.x + p.y * p.y;
        }
#pragma unroll
        for (int o = 4; o > 0; o >>= 1) {
            s += __shfl_xor_sync(0xffffffffu, s, o);
            s2 += __shfl_xor_sync(0xffffffffu, s2, o);
        }
        if (g.og == 0) {
            sRed[(g.eRow0 + i) * 4 + g.ocblk * 2 + 0] = s;
            sRed[(g.eRow0 + i) * 4 + g.ocblk * 2 + 1] = s2;
        }
    }
    __syncthreads();
#pragma unroll
    for (int i = 0; i < 4; i++) {
        const int e = g.eRow0 + i;
        const float s = sRed[e * 4 + 0] + sRed[e * 4 + 2];
        const float s2 = sRed[e * 4 + 1] + sRed[e * 4 + 3];
        const float mu = s * (1.f / 128.f);
        const float var = s2 * (1.f / 128.f) - mu * mu;
        const float rstd = rsqrtf(var + GN_EPS);
        float v[8];
#pragma unroll
        for (int j = 0; j < 4; j++) {
            float2 p = unpack2(acc[i][j]);
            v[2 * j] = p.x;
            v[2 * j + 1] = p.y;
        }
        float y[8];
        y[0] = (v[0] - mu) * rstd * g0.x + b0.x;
        y[1] = (v[1] - mu) * rstd * g0.y + b0.y;
        y[2] = (v[2] - mu) * rstd * g0.z + b0.z;
        y[3] = (v[3] - mu) * rstd * g0.w + b0.w;
        y[4] = (v[4] - mu) * rstd * g1.x + b1.x;
        y[5] = (v[5] - mu) * rstd * g1.y + b1.y;
        y[6] = (v[6] - mu) * rstd * g1.z + b1.z;
        y[7] = (v[7] - mu) * rstd * g1.w + b1.w;
        if (MODE == 2) {
            const float4 r0 = *(const float4*)(res + (size_t)e * DD + g.o0);
            const float4 r1 = *(const float4*)(res + (size_t)e * DD + g.o0 + 4);
            y[0] += r0.x; y[1] += r0.y; y[2] += r0.z; y[3] += r0.w;
            y[4] += r1.x; y[5] += r1.y; y[6] += r1.z; y[7] += r1.w;
        }
#pragma unroll
        for (int j = 0; j < 8; j++) y[j] = fmaxf(y[j], 0.f);
        *(float4*)(dst + (size_t)e * dstStride + g.o0) = make_float4(y[0], y[1], y[2], y[3]);
        *(float4*)(dst + (size_t)e * dstStride + g.o0 + 4) = make_float4(y[4], y[5], y[6], y[7]);
    }
}

__device__ __forceinline__ void store_acc_raw(const unsigned long long (&acc)[4][4],
                                              float* dst, int stride, const TG& g) {
#pragma unroll
    for (int i = 0; i < 4; i++) {
        float v[8];
#pragma unroll
        for (int j = 0; j < 4; j++) {
            float2 p = unpack2(acc[i][j]);
            v[2 * j] = p.x;
            v[2 * j + 1] = p.y;
        }
        float* d = dst + (size_t)(g.eRow0 + i) * stride + g.o0;
        *(float4*)(d) = make_float4(v[0], v[1], v[2], v[3]);
        *(float4*)(d + 4) = make_float4(v[4], v[5], v[6], v[7]);
    }
}

#define ZACC(acc)                                          \
    _Pragma("unroll") for (int _i = 0; _i < 4; _i++)       \
        _Pragma("unroll") for (int _j = 0; _j < 4; _j++)   \
            acc[_i][_j] = 0ull;

// ---------- node precompute: g_nc = nodes @ ctx0_Wc^T ----------
__global__ void __launch_bounds__(NTH, 2)
node_kernel(const float* __restrict__ nodes, const float* __restrict__ c0Wc) {
    extern __shared__ float sm[];
    float* sA = sm;
    float* sW = sA + TILE * STR;
    const TG g = tgeom();
    const int r0 = blockIdx.x * TILE;
    for (int idx = g.t; idx < TILE * 32; idx += NTH) {
        int e = idx >> 5, c4 = idx & 31;
        *(float4*)(sA + e * STR + c4 * 4) =
            *(const float4*)(nodes + (size_t)(r0 + e) * DD + c4 * 4);
    }
    __syncthreads();
    unsigned long long acc[4][4];
    ZACC(acc);
    gemm4x8(c0Wc, 3 * DD, sA, sW, acc, g);
    store_acc_raw(acc, g_nc + (size_t)r0 * DD, DD, g);
}

// ---------- actor pre: q=relu(gn(actors@qW^T)); g_qc=q@ctx0_Wq^T; g_a=actors@agtW^T ----------
__global__ void __launch_bounds__(NTH, 2)
pre_kernel(const float* __restrict__ actors_in, const float* __restrict__ qW,
           const float* __restrict__ qg, const float* __restrict__ qb,
           const float* __restrict__ c0Wq, const float* __restrict__ aW, int blk) {
    extern __shared__ float sm[];
    float* sA = sm;                   // [64][132]
    float* sQ = sA + TILE * STR;      // [64][132]
    float* sW = sQ + TILE * STR;      // 2 x [16][128]
    float* sRed = sW + 2 * SWBUF;     // [64][4]
    const float* cur = blk ? g_actors : actors_in;
    const TG g = tgeom();
    const int r0 = blockIdx.x * TILE;
    for (int idx = g.t; idx < TILE * 32; idx += NTH) {
        int e = idx >> 5, c4 = idx & 31;
        *(float4*)(sA + e * STR + c4 * 4) =
            *(const float4*)(cur + (size_t)(r0 + e) * DD + c4 * 4);
    }
    __syncthreads();
    unsigned long long acc[4][4];
    ZACC(acc);
    gemm4x8(qW, DD, sA, sW, acc, g);
    gn_regs<1>(acc, sQ, STR, qg, qb, sRed, g, nullptr);
    ZACC(acc);
    gemm4x8(c0Wq, 3 * DD, sQ, sW, acc, g);   // chunk-0 sync orders sQ writes
    store_acc_raw(acc, g_qc + (size_t)r0 * DD, DD, g);
    ZACC(acc);
    gemm4x8(aW, DD, sA, sW, acc, g);
    store_acc_raw(acc, g_a + (size_t)r0 * DD, DD, g);
}

// ---------- fused edge pipeline (3 GEMM units) ----------
__global__ void __launch_bounds__(NTH, 2)
edge_kernel(const float* __restrict__ actor_ctrs, const float* __restrict__ node_ctrs,
            const int* __restrict__ hi, const int* __restrict__ wi,
            const float* __restrict__ d0W, const float* __restrict__ d0b,
            const float* __restrict__ d1W, const float* __restrict__ d1g,
            const float* __restrict__ d1b,
            const float* __restrict__ c0Wd, const float* __restrict__ c0g,
            const float* __restrict__ c0b, const float* __restrict__ c1W) {
    extern __shared__ float sm[];
    float* sD = sm;                   // [64][132]: H1 -> gn(dist1) -> gn(ctx0)
    float* sM = sD + TILE * STR;      // [64][132]: qc[hi]+nc[wi]
    float* sW = sM + TILE * STR;      // 2 x [16][128]
    float* sRed = sW + 2 * SWBUF;     // [64][4]
    int* shi = (int*)(sRed + TILE * 4);
    int* swi = shi + TILE;
    float* sdx = (float*)(swi + TILE);
    float* sdy = sdx + TILE;

    const TG g = tgeom();
    const int t = g.t;
    const int e0 = blockIdx.x * TILE;
    if (t < TILE) {
        int h = hi[e0 + t], w = wi[e0 + t];
        shi[t] = h;
        swi[t] = w;
        sdx[t] = actor_ctrs[2 * h] - node_ctrs[2 * w];
        sdy[t] = actor_ctrs[2 * h + 1] - node_ctrs[2 * w + 1];
    }
    __syncthreads();
    // gather precomputed ctx0 q+c contributions (L2-resident)
#pragma unroll 4
    for (int idx = t; idx < TILE * 32; idx += NTH) {
        int e = idx >> 5, c4 = idx & 31;
        const float4 a = *(const float4*)(g_qc + (size_t)shi[e] * DD + c4 * 4);
        const float4 b = *(const float4*)(g_nc + (size_t)swi[e] * DD + c4 * 4);
        *(float4*)(sM + e * STR + c4 * 4) =
            make_float4(a.x + b.x, a.y + b.y, a.z + b.z, a.w + b.w);
    }
    // H1 = relu(dist0(dvec)) -> sD
    for (int idx = t; idx < TILE * DD; idx += NTH) {
        int e = idx >> 7, ch = idx & 127;
        float v = fmaf(d0W[2 * ch], sdx[e], fmaf(d0W[2 * ch + 1], sdy[e], d0b[ch]));
        sD[e * STR + ch] = fmaxf(v, 0.f);
    }
    __syncthreads();

    unsigned long long acc[4][4];
    // d = relu(gn(H1 @ dist1^T)) -> sD
    ZACC(acc);
    gemm4x8(d1W, DD, sD, sW, acc, g);
    gn_regs<1>(acc, sD, STR, d1g, d1b, sRed, g, nullptr);
    // ctx0: acc = qc[hi]+nc[wi] (from sM) + d @ c0Wd^T; then gn-relu -> sD
#pragma unroll
    for (int i = 0; i < 4; i++) {
        const float* m = sM + (g.eRow0 + i) * STR + g.o0;
        const float4 u0 = *(const float4*)(m);
        const float4 u1 = *(const float4*)(m + 4);
        acc[i][0] = packf2(u0.x, u0.y);
        acc[i][1] = packf2(u0.z, u0.w);
        acc[i][2] = packf2(u1.x, u1.y);
        acc[i][3] = packf2(u1.z, u1.w);
    }
    gemm4x8(c0Wd, 3 * DD, sD, sW, acc, g);   // chunk-0 sync orders sD writes
    gn_regs<1>(acc, sD, STR, c0g, c0b, sRed, g, nullptr);
    // ctx1 -> scatter-add from registers
    ZACC(acc);
    gemm4x8(c1W, DD, sD, sW, acc, g);
#pragma unroll
    for (int i = 0; i < 4; i++) {
        float v[8];
#pragma unroll
        for (int j = 0; j < 4; j++) {
            float2 p = unpack2(acc[i][j]);
            v[2 * j] = p.x;
            v[2 * j + 1] = p.y;
        }
        const float* p = g_a + (size_t)shi[g.eRow0 + i] * DD + g.o0;
        redv4(p, v[0], v[1], v[2], v[3]);
        redv4(p + 4, v[4], v[5], v[6], v[7]);
    }
}

// ---------- actor post: a=relu(gn(a)); a=gn(a@linW^T); out=relu(a+res) ----------
__global__ void __launch_bounds__(NTH, 2)
post_kernel(const float* __restrict__ actors_in, const float* __restrict__ ng,
            const float* __restrict__ nb, const float* __restrict__ lW,
            const float* __restrict__ lg, const float* __restrict__ lb,
            float* __restrict__ out, int blk) {
    extern __shared__ float sm[];
    float* sA = sm;
    float* sW = sA + TILE * STR;
    float* sRed = sW + 2 * SWBUF;
    const float* cur = blk ? g_actors : actors_in;
    float* nxt = blk ? out : g_actors;
    const TG g = tgeom();
    const int t = g.t;
    const int r0 = blockIdx.x * TILE;
    {
        const int warp = t >> 5, lane = t & 31;
        for (int e = warp; e < TILE; e += 8) {
            const float* row = g_a + (size_t)(r0 + e) * DD;
            float v[4], s = 0.f, s2 = 0.f;
#pragma unroll
            for (int j = 0; j < 4; j++) {
                v[j] = row[lane + 32 * j];
                s += v[j];
                s2 += v[j] * v[j];
            }
#pragma unroll
            for (int o = 16; o > 0; o >>= 1) {
                s += __shfl_xor_sync(0xffffffffu, s, o);
                s2 += __shfl_xor_sync(0xffffffffu, s2, o);
            }
            const float mu = s * (1.f / 128.f);
            const float var = s2 * (1.f / 128.f) - mu * mu;
            const float rstd = rsqrtf(var + GN_EPS);
#pragma unroll
            for (int j = 0; j < 4; j++) {
                const int ch = lane + 32 * j;
                sA[e * STR + ch] = fmaxf((v[j] - mu) * rstd * ng[ch] + nb[ch], 0.f);
            }
        }
    }
    __syncthreads();
    unsigned long long acc[4][4];
    ZACC(acc);
    gemm4x8(lW, DD, sA, sW, acc, g);
    gn_regs<2>(acc, nxt + (size_t)r0 * DD, DD, lg, lb, sRed, g, cur + (size_t)r0 * DD);
}

#define SMEM_PRE ((2 * TILE * STR + 2 * SWBUF + TILE * 4) * 4)
#define SMEM_NODE ((TILE * STR + 2 * SWBUF) * 4)
#define SMEM_EDGE ((2 * TILE * STR + 2 * SWBUF + TILE * 4) * 4 + TILE * 4 * 4)
#define SMEM_POST ((TILE * STR + 2 * SWBUF + TILE * 4) * 4)

extern "C" void kernel_launch(void* const* d_in, const int* in_sizes, int n_in,
                              void* d_out, int out_size) {
    (void)in_sizes; (void)n_in; (void)out_size;
    const float* actors = (const float*)d_in[0];
    const float* nodes = (const float*)d_in[1];
    const float* actor_ctrs = (const float*)d_in[2];
    const float* node_ctrs = (const float*)d_in[3];
    const int* hi = (const int*)d_in[4];
    const int* wi = (const int*)d_in[5];
    const float* d0W = (const float*)d_in[6];
    const float* d0b = (const float*)d_in[7];
    const float* d1W = (const float*)d_in[8];
    const float* d1g = (const float*)d_in[9];
    const float* d1b = (const float*)d_in[10];
    const float* qW = (const float*)d_in[11];
    const float* qg = (const float*)d_in[12];
    const float* qb = (const float*)d_in[13];
    const float* c0W = (const float*)d_in[14];
    const float* c0g = (const float*)d_in[15];
    const float* c0b = (const float*)d_in[16];
    const float* c1W = (const float*)d_in[17];
    const float* aW = (const float*)d_in[18];
    const float* ng = (const float*)d_in[19];
    const float* nb = (const float*)d_in[20];
    const float* lW = (const float*)d_in[21];
    const float* lg = (const float*)d_in[22];
    const float* lb = (const float*)d_in[23];
    float* out = (float*)d_out;

    cudaFuncSetAttribute(pre_kernel, cudaFuncAttributeMaxDynamicSharedMemorySize, SMEM_PRE);
    cudaFuncSetAttribute(node_kernel, cudaFuncAttributeMaxDynamicSharedMemorySize, SMEM_NODE);
    cudaFuncSetAttribute(edge_kernel, cudaFuncAttributeMaxDynamicSharedMemorySize, SMEM_EDGE);
    cudaFuncSetAttribute(post_kernel, cudaFuncAttributeMaxDynamicSharedMemorySize, SMEM_POST);

    for (int blk = 0; blk < 2; blk++) {
        const int off = blk * DD;
        const float* c0Wb = c0W + (size_t)blk * DD * 3 * DD;
        node_kernel<<<NN / TILE, NTH, SMEM_NODE>>>(nodes, c0Wb + 2 * DD);
        pre_kernel<<<NA / TILE, NTH, SMEM_PRE>>>(actors, qW + blk * DD * DD, qg + off, qb + off,
                                                 c0Wb + DD, aW + blk * DD * DD, blk);
        edge_kernel<<<NE / TILE, NTH, SMEM_EDGE>>>(
            actor_ctrs, node_ctrs, hi, wi,
            d0W + blk * DD * 2, d0b + off,
            d1W + blk * DD * DD, d1g + off, d1b + off,
            c0Wb, c0g + off, c0b + off,
            c1W + blk * DD * DD);
        post_kernel<<<NA / TILE, NTH, SMEM_POST>>>(actors, ng + off, nb + off, lW + blk * DD * DD,
                                                   lg + off, lb + off, out, blk);
    }
}

// round 16
// speedup vs baseline: 2.0418x; 2.0418x over previous
#include <cuda_runtime.h>
#include <cuda_bf16.h>
#include <cstdint>

#define NA 8192
#define NN 65536
#define NE 262144
#define DD 128
#define GN_EPS 1e-5f
#define TILE 128
#define STR 132
#define NTH 256
#define WCH 16
#define SWBUF (WCH * 128)

// ---------------- scratch (device globals) ----------------
__device__ __align__(16) float g_qc[NA * DD];
__device__ __align__(16) float g_nc[NN * DD];
__device__ __align__(16) float g_a[NA * DD];
__device__ __align__(16) float g_actors[NA * DD];
// pre-split bf16 weights, row-major [oc][k]: [mat][hi/lo][16384]
__device__ __align__(16) __nv_bfloat16 g_w[3][2][16384];

// ---------------- small helpers ----------------
__device__ __forceinline__ uint32_t smem_to_u32(const void* p) {
    uint32_t a;
    asm("{ .reg .u64 t; cvta.to.shared.u64 t, %1; cvt.u32.u64 %0, t; }" : "=r"(a) : "l"(p));
    return a;
}
__device__ __forceinline__ void redv4(const float* p, float a, float b, float c, float d) {
    asm volatile("red.global.add.v4.f32 [%0], {%1, %2, %3, %4};"
                 :: "l"(p), "f"(a), "f"(b), "f"(c), "f"(d) : "memory");
}
__device__ __forceinline__ void redv2(const float* p, float a, float b) {
    asm volatile("red.global.add.v2.f32 [%0], {%1, %2};"
                 :: "l"(p), "f"(a), "f"(b) : "memory");
}
__device__ __forceinline__ void bf16_split(float v, __nv_bfloat16& h, __nv_bfloat16& l) {
    h = __float2bfloat16_rn(v);
    l = __float2bfloat16_rn(v - __bfloat162float(h));
}
__device__ __forceinline__ uint32_t pkbf(__nv_bfloat16 a, __nv_bfloat16 b) {
    return (uint32_t)__bfloat16_as_ushort(a) | ((uint32_t)__bfloat16_as_ushort(b) << 16);
}
__device__ __forceinline__ void ldsm_x4(uint32_t& r0, uint32_t& r1, uint32_t& r2, uint32_t& r3,
                                        uint32_t addr) {
    asm volatile("ldmatrix.sync.aligned.m8n8.x4.shared.b16 {%0,%1,%2,%3}, [%4];"
                 : "=r"(r0), "=r"(r1), "=r"(r2), "=r"(r3) : "r"(addr));
}
__device__ __forceinline__ void ldsm_x2(uint32_t& r0, uint32_t& r1, uint32_t addr) {
    asm volatile("ldmatrix.sync.aligned.m8n8.x2.shared.b16 {%0,%1}, [%2];"
                 : "=r"(r0), "=r"(r1) : "r"(addr));
}
__device__ __forceinline__ void mma16816(float* c, uint32_t a0, uint32_t a1, uint32_t a2,
                                         uint32_t a3, uint32_t b0, uint32_t b1) {
    asm volatile("mma.sync.aligned.m16n8k16.row.col.f32.bf16.bf16.f32 "
                 "{%0,%1,%2,%3}, {%4,%5,%6,%7}, {%8,%9}, {%0,%1,%2,%3};"
                 : "+f"(c[0]), "+f"(c[1]), "+f"(c[2]), "+f"(c[3])
                 : "r"(a0), "r"(a1), "r"(a2), "r"(a3), "r"(b0), "r"(b1));
}

// ================= scalar fp32 machinery (R8, known good) =================
__device__ __forceinline__ void ffma2(unsigned long long& acc, unsigned long long w,
                                      unsigned long long a) {
    asm volatile("fma.rn.f32x2 %0, %1, %2, %0;" : "+l"(acc) : "l"(w), "l"(a));
}
__device__ __forceinline__ unsigned long long pack2(float x) {
    unsigned long long r;
    asm("mov.b64 %0, {%1, %1};" : "=l"(r) : "f"(x));
    return r;
}
__device__ __forceinline__ float2 unpack2(unsigned long long v) {
    float2 r;
    asm("mov.b64 {%0, %1}, %2;" : "=f"(r.x), "=f"(r.y) : "l"(v));
    return r;
}
struct TG {
    int t, lane, og, ocblk, eRow0, o0;
};
__device__ __forceinline__ TG tgeom() {
    TG g;
    g.t = threadIdx.x;
    const int warp = g.t >> 5;
    g.lane = g.t & 31;
    g.og = g.lane & 7;
    g.ocblk = warp & 1;
    g.eRow0 = (warp >> 1) * 32 + (g.lane >> 3) * 8;
    g.o0 = g.ocblk * 64 + g.og * 8;
    return g;
}
__device__ __forceinline__ void gemm8x8(const float* __restrict__ W, int ldW,
                                        const float* sAct, float* sW,
                                        unsigned long long (&acc)[8][4], const TG& g) {
    const int oc = g.t & 127;
    const int kh = (g.t >> 7) * 8;
    const int nch = DD >> 4;
    float4 w0 = *(const float4*)(W + oc * ldW + kh);
    float4 w1 = *(const float4*)(W + oc * ldW + kh + 4);
    for (int c = 0; c < nch; c++) {
        float* sb = sW + (c & 1) * SWBUF;
        sb[(kh + 0) * 128 + oc] = w0.x;
        sb[(kh + 1) * 128 + oc] = w0.y;
        sb[(kh + 2) * 128 + oc] = w0.z;
        sb[(kh + 3) * 128 + oc] = w0.w;
        sb[(kh + 4) * 128 + oc] = w1.x;
        sb[(kh + 5) * 128 + oc] = w1.y;
        sb[(kh + 6) * 128 + oc] = w1.z;
        sb[(kh + 7) * 128 + oc] = w1.w;
        __syncthreads();
        if (c + 1 < nch) {
            const float* Wp = W + oc * ldW + ((c + 1) << 4) + kh;
            w0 = *(const float4*)(Wp);
            w1 = *(const float4*)(Wp + 4);
        }
        const int k0 = c << 4;
#pragma unroll
        for (int kq = 0; kq < 4; kq++) {
            float4 a4[8];
#pragma unroll
            for (int i = 0; i < 8; i++)
                a4[i] = *(const float4*)(sAct + (g.eRow0 + i) * STR + k0 + kq * 4);
#pragma unroll
            for (int kk = 0; kk < 4; kk++) {
                const int k = kq * 4 + kk;
                const ulonglong2 wa = *(const ulonglong2*)(sb + k * 128 + g.o0);
                const ulonglong2 wb = *(const ulonglong2*)(sb + k * 128 + g.o0 + 4);
#pragma unroll
                for (int i = 0; i < 8; i++) {
                    const float av = (kk == 0) ? a4[i].x : (kk == 1) ? a4[i].y
                                   : (kk == 2) ? a4[i].z : a4[i].w;
                    const unsigned long long aa = pack2(av);
                    ffma2(acc[i][0], wa.x, aa);
                    ffma2(acc[i][1], wa.y, aa);
                    ffma2(acc[i][2], wb.x, aa);
                    ffma2(acc[i][3], wb.y, aa);
                }
            }
        }
    }
}
template <int MODE>
__device__ __forceinline__ void gn_regs(const unsigned long long (&acc)[8][4],
                                        float* dst, int dstStride,
                                        const float* __restrict__ gamma,
                                        const float* __restrict__ beta,
                                        float* sRed, const TG& g, const float* res) {
    const float4 g0 = *(const float4*)(gamma + g.o0);
    const float4 g1 = *(const float4*)(gamma + g.o0 + 4);
    const float4 b0 = *(const float4*)(beta + g.o0);
    const float4 b1 = *(const float4*)(beta + g.o0 + 4);
#pragma unroll
    for (int i = 0; i < 8; i++) {
        float s = 0.f, s2 = 0.f;
#pragma unroll
        for (int j = 0; j < 4; j++) {
            float2 p = unpack2(acc[i][j]);
            s += p.x + p.y;
            s2 += p.x * p.x + p.y * p.y;
        }
#pragma unroll
        for (int o = 4; o > 0; o >>= 1) {
            s += __shfl_xor_sync(0xffffffffu, s, o);
            s2 += __shfl_xor_sync(0xffffffffu, s2, o);
        }
        if (g.og == 0) {
            sRed[(g.eRow0 + i) * 4 + g.ocblk * 2 + 0] = s;
            sRed[(g.eRow0 + i) * 4 + g.ocblk * 2 + 1] = s2;
        }
    }
    __syncthreads();
#pragma unroll
    for (int i = 0; i < 8; i++) {
        const int e = g.eRow0 + i;
        const float s = sRed[e * 4 + 0] + sRed[e * 4 + 2];
        const float s2 = sRed[e * 4 + 1] + sRed[e * 4 + 3];
        const float mu = s * (1.f / 128.f);
        const float var = s2 * (1.f / 128.f) - mu * mu;
        const float rstd = rsqrtf(var + GN_EPS);
        float v[8];
#pragma unroll
        for (int j = 0; j < 4; j++) {
            float2 p = unpack2(acc[i][j]);
            v[2 * j] = p.x;
            v[2 * j + 1] = p.y;
        }
        float y[8];
        y[0] = (v[0] - mu) * rstd * g0.x + b0.x;
        y[1] = (v[1] - mu) * rstd * g0.y + b0.y;
        y[2] = (v[2] - mu) * rstd * g0.z + b0.z;
        y[3] = (v[3] - mu) * rstd * g0.w + b0.w;
        y[4] = (v[4] - mu) * rstd * g1.x + b1.x;
        y[5] = (v[5] - mu) * rstd * g1.y + b1.y;
        y[6] = (v[6] - mu) * rstd * g1.z + b1.z;
        y[7] = (v[7] - mu) * rstd * g1.w + b1.w;
        if (MODE == 2) {
            const float4 r0 = *(const float4*)(res + (size_t)e * DD + g.o0);
            const float4 r1 = *(const float4*)(res + (size_t)e * DD + g.o0 + 4);
            y[0] += r0.x; y[1] += r0.y; y[2] += r0.z; y[3] += r0.w;
            y[4] += r1.x; y[5] += r1.y; y[6] += r1.z; y[7] += r1.w;
        }
#pragma unroll
        for (int j = 0; j < 8; j++) y[j] = fmaxf(y[j], 0.f);
        *(float4*)(dst + (size_t)e * dstStride + g.o0) = make_float4(y[0], y[1], y[2], y[3]);
        *(float4*)(dst + (size_t)e * dstStride + g.o0 + 4) = make_float4(y[4], y[5], y[6], y[7]);
    }
}
__device__ __forceinline__ void store_acc_raw(const unsigned long long (&acc)[8][4],
                                              float* dst, int stride, const TG& g) {
#pragma unroll
    for (int i = 0; i < 8; i++) {
        float v[8];
#pragma unroll
        for (int j = 0; j < 4; j++) {
            float2 p = unpack2(acc[i][j]);
            v[2 * j] = p.x;
            v[2 * j + 1] = p.y;
        }
        float* d = dst + (size_t)(g.eRow0 + i) * stride + g.o0;
        *(float4*)(d) = make_float4(v[0], v[1], v[2], v[3]);
        *(float4*)(d + 4) = make_float4(v[4], v[5], v[6], v[7]);
    }
}
#define ZACC8(acc)                                         \
    _Pragma("unroll") for (int _i = 0; _i < 8; _i++)       \
        _Pragma("unroll") for (int _j = 0; _j < 4; _j++)   \
            acc[_i][_j] = 0ull;

// ---------------- node / pre / post (scalar fp32) ----------------
__global__ void __launch_bounds__(NTH, 1)
node_kernel(const float* __restrict__ nodes, const float* __restrict__ c0Wc) {
    extern __shared__ float sm[];
    float* sA = sm;
    float* sW = sA + TILE * STR;
    const TG g = tgeom();
    const int r0 = blockIdx.x * TILE;
    for (int idx = g.t; idx < TILE * 32; idx += NTH) {
        int e = idx >> 5, c4 = idx & 31;
        *(float4*)(sA + e * STR + c4 * 4) =
            *(const float4*)(nodes + (size_t)(r0 + e) * DD + c4 * 4);
    }
    __syncthreads();
    unsigned long long acc[8][4];
    ZACC8(acc);
    gemm8x8(c0Wc, 3 * DD, sA, sW, acc, g);
    store_acc_raw(acc, g_nc + (size_t)r0 * DD, DD, g);
}

__global__ void __launch_bounds__(NTH, 1)
pre_kernel(const float* __restrict__ actors_in, const float* __restrict__ qW,
           const float* __restrict__ qg, const float* __restrict__ qb,
           const float* __restrict__ c0Wq, const float* __restrict__ aW, int blk) {
    extern __shared__ float sm[];
    float* sA = sm;
    float* sQ = sA + TILE * STR;
    float* sW = sQ + TILE * STR;
    float* sRed = sW + 2 * SWBUF;
    const float* cur = blk ? g_actors : actors_in;
    const TG g = tgeom();
    const int r0 = blockIdx.x * TILE;
    for (int idx = g.t; idx < TILE * 32; idx += NTH) {
        int e = idx >> 5, c4 = idx & 31;
        *(float4*)(sA + e * STR + c4 * 4) =
            *(const float4*)(cur + (size_t)(r0 + e) * DD + c4 * 4);
    }
    __syncthreads();
    unsigned long long acc[8][4];
    ZACC8(acc);
    gemm8x8(qW, DD, sA, sW, acc, g);
    gn_regs<1>(acc, sQ, STR, qg, qb, sRed, g, nullptr);
    ZACC8(acc);
    gemm8x8(c0Wq, 3 * DD, sQ, sW, acc, g);
    store_acc_raw(acc, g_qc + (size_t)r0 * DD, DD, g);
    ZACC8(acc);
    gemm8x8(aW, DD, sA, sW, acc, g);
    store_acc_raw(acc, g_a + (size_t)r0 * DD, DD, g);
}

__global__ void __launch_bounds__(NTH, 1)
post_kernel(const float* __restrict__ actors_in, const float* __restrict__ ng,
            const float* __restrict__ nb, const float* __restrict__ lW,
            const float* __restrict__ lg, const float* __restrict__ lb,
            float* __restrict__ out, int blk) {
    extern __shared__ float sm[];
    float* sA = sm;
    float* sW = sA + TILE * STR;
    float* sRed = sW + 2 * SWBUF;
    const float* cur = blk ? g_actors : actors_in;
    float* nxt = blk ? out : g_actors;
    const TG g = tgeom();
    const int t = g.t;
    const int r0 = blockIdx.x * TILE;
    {
        const int warp = t >> 5, lane = t & 31;
        for (int e = warp; e < TILE; e += 8) {
            const float* row = g_a + (size_t)(r0 + e) * DD;
            float v[4], s = 0.f, s2 = 0.f;
#pragma unroll
            for (int j = 0; j < 4; j++) {
                v[j] = row[lane + 32 * j];
                s += v[j];
                s2 += v[j] * v[j];
            }
#pragma unroll
            for (int o = 16; o > 0; o >>= 1) {
                s += __shfl_xor_sync(0xffffffffu, s, o);
                s2 += __shfl_xor_sync(0xffffffffu, s2, o);
            }
            const float mu = s * (1.f / 128.f);
            const float var = s2 * (1.f / 128.f) - mu * mu;
            const float rstd = rsqrtf(var + GN_EPS);
#pragma unroll
            for (int j = 0; j < 4; j++) {
                const int ch = lane + 32 * j;
                sA[e * STR + ch] = fmaxf((v[j] - mu) * rstd * ng[ch] + nb[ch], 0.f);
            }
        }
    }
    __syncthreads();
    unsigned long long acc[8][4];
    ZACC8(acc);
    gemm8x8(lW, DD, sA, sW, acc, g);
    gn_regs<2>(acc, nxt + (size_t)r0 * DD, DD, lg, lb, sRed, g, cur + (size_t)r0 * DD);
}

// ---------------- weight prep: split fp32 -> bf16 hi/lo (row-major [oc][k]) ----------------
__global__ void __launch_bounds__(256, 4)
wprep_kernel(const float* __restrict__ d1W, const float* __restrict__ c0Wd,
             const float* __restrict__ c1W) {
    const int idx = blockIdx.x * 256 + threadIdx.x;  // 3*16384
    const int m = idx / 16384, e = idx % 16384;
    const int row = e >> 7, col = e & 127;
    float v;
    if (m == 0) v = d1W[row * 128 + col];
    else if (m == 1) v = c0Wd[row * 384 + col];
    else v = c1W[row * 128 + col];
    __nv_bfloat16 h, l;
    bf16_split(v, h, l);
    g_w[m][0][e] = h;
    g_w[m][1][e] = l;
}

// ---------------- mma.sync edge kernel ----------------
// smem (bytes): padded bf16 tiles use row stride 272B (136 bf16) for conflict-free ldmatrix
#define RSB 272
#define ABYTES (128 * RSB)  // 34816
#define OFF_AH 0
#define OFF_AL ABYTES
#define OFF_WH (2 * ABYTES)
#define OFF_WL (3 * ABYTES)
#define OFF_M (4 * ABYTES)               // float [128][132] = 67584
#define OFF_HI (OFF_M + TILE * STR * 4)
#define OFF_WI (OFF_HI + 512)
#define OFF_DX (OFF_WI + 512)
#define OFF_DY (OFF_DX + 512)
#define SMEM_EDGE (OFF_DY + 512)

__device__ __forceinline__ void copy_w(char* sWh, char* sWl, int mat, int t) {
    const uint4* sh = (const uint4*)&g_w[mat][0][0];
    const uint4* sl = (const uint4*)&g_w[mat][1][0];
    for (int i = t; i < 2048; i += NTH) {
        const int row = i >> 4, cc = i & 15;
        *(uint4*)(sWh + row * RSB + cc * 16) = sh[i];
        *(uint4*)(sWl + row * RSB + cc * 16) = sl[i];
    }
}

__device__ __forceinline__ void wgemm(float (&acc)[16][4], uint32_t aH, uint32_t aL,
                                      uint32_t wH, uint32_t wL, int lane) {
    const uint32_t ao = (uint32_t)((lane & 15) * RSB + ((lane >> 4) & 1) * 16);
    const uint32_t bo = (uint32_t)((lane & 7) * RSB + ((lane >> 3) & 1) * 16);
#pragma unroll
    for (int k = 0; k < 8; k++) {
        const uint32_t kb = (uint32_t)k * 32;
        uint32_t ah0, ah1, ah2, ah3, al0, al1, al2, al3;
        ldsm_x4(ah0, ah1, ah2, ah3, aH + ao + kb);
        ldsm_x4(al0, al1, al2, al3, aL + ao + kb);
#pragma unroll
        for (int nt = 0; nt < 16; nt++) {
            uint32_t bh0, bh1, bl0, bl1;
            ldsm_x2(bh0, bh1, wH + nt * (8u * RSB) + bo + kb);
            ldsm_x2(bl0, bl1, wL + nt * (8u * RSB) + bo + kb);
            mma16816(acc[nt], ah0, ah1, ah2, ah3, bh0, bh1);
            mma16816(acc[nt], ah0, ah1, ah2, ah3, bl0, bl1);
            mma16816(acc[nt], al0, al1, al2, al3, bh0, bh1);
        }
    }
}

// GroupNorm from mma accumulators (warp owns rows r0..r0+15); write split bf16 to A tiles
template <bool ADDM>
__device__ __forceinline__ void gn_mma(float (&acc)[16][4], const float* sM,
                                       const float* __restrict__ gamma,
                                       const float* __restrict__ beta,
                                       char* sAh, char* sAl, int r0, int lane) {
    const int rlo = r0 + (lane >> 2), rhi = rlo + 8;
    const int cb = 2 * (lane & 3);
    if (ADDM) {
#pragma unroll
        for (int nt = 0; nt < 16; nt++) {
            const int col = nt * 8 + cb;
            const float2 mlo = *(const float2*)(sM + rlo * STR + col);
            const float2 mhi = *(const float2*)(sM + rhi * STR + col);
            acc[nt][0] += mlo.x;
            acc[nt][1] += mlo.y;
            acc[nt][2] += mhi.x;
            acc[nt][3] += mhi.y;
        }
    }
    float sl = 0.f, s2l = 0.f, sh = 0.f, s2h = 0.f;
#pragma unroll
    for (int nt = 0; nt < 16; nt++) {
        sl += acc[nt][0] + acc[nt][1];
        s2l += acc[nt][0] * acc[nt][0] + acc[nt][1] * acc[nt][1];
        sh += acc[nt][2] + acc[nt][3];
        s2h += acc[nt][2] * acc[nt][2] + acc[nt][3] * acc[nt][3];
    }
#pragma unroll
    for (int o = 1; o <= 2; o <<= 1) {  // reduce over the 4 lanes sharing a row
        sl += __shfl_xor_sync(0xffffffffu, sl, o);
        s2l += __shfl_xor_sync(0xffffffffu, s2l, o);
        sh += __shfl_xor_sync(0xffffffffu, sh, o);
        s2h += __shfl_xor_sync(0xffffffffu, s2h, o);
    }
    const float mul = sl * (1.f / 128.f);
    const float rsl = rsqrtf(s2l * (1.f / 128.f) - mul * mul + GN_EPS);
    const float muh = sh * (1.f / 128.f);
    const float rsh = rsqrtf(s2h * (1.f / 128.f) - muh * muh + GN_EPS);
#pragma unroll
    for (int nt = 0; nt < 16; nt++) {
        const int col = nt * 8 + cb;
        const float2 g2 = *(const float2*)(gamma + col);
        const float2 b2 = *(const float2*)(beta + col);
        const float y0 = fmaxf((acc[nt][0] - mul) * rsl * g2.x + b2.x, 0.f);
        const float y1 = fmaxf((acc[nt][1] - mul) * rsl * g2.y + b2.y, 0.f);
        const float y2 = fmaxf((acc[nt][2] - muh) * rsh * g2.x + b2.x, 0.f);
        const float y3 = fmaxf((acc[nt][3] - muh) * rsh * g2.y + b2.y, 0.f);
        __nv_bfloat16 h0, l0, h1, l1, h2, l2, h3, l3;
        bf16_split(y0, h0, l0);
        bf16_split(y1, h1, l1);
        bf16_split(y2, h2, l2);
        bf16_split(y3, h3, l3);
        *(uint32_t*)(sAh + rlo * RSB + col * 2) = pkbf(h0, h1);
        *(uint32_t*)(sAl + rlo * RSB + col * 2) = pkbf(l0, l1);
        *(uint32_t*)(sAh + rhi * RSB + col * 2) = pkbf(h2, h3);
        *(uint32_t*)(sAl + rhi * RSB + col * 2) = pkbf(l2, l3);
    }
}

#define ZACC16(acc)                                        \
    _Pragma("unroll") for (int _i = 0; _i < 16; _i++)      \
        _Pragma("unroll") for (int _j = 0; _j < 4; _j++)   \
            acc[_i][_j] = 0.f;

__global__ void __launch_bounds__(NTH, 1)
edge_kernel(const float* __restrict__ actor_ctrs, const float* __restrict__ node_ctrs,
            const int* __restrict__ hi, const int* __restrict__ wi,
            const float* __restrict__ d0W, const float* __restrict__ d0b,
            const float* __restrict__ d1g, const float* __restrict__ d1b,
            const float* __restrict__ c0g, const float* __restrict__ c0b) {
    extern __shared__ char smc[];
    const uint32_t sb = smem_to_u32(smc);
    char* sAh = smc + OFF_AH;
    char* sAl = smc + OFF_AL;
    char* sWh = smc + OFF_WH;
    char* sWl = smc + OFF_WL;
    float* sM = (float*)(smc + OFF_M);
    int* shi = (int*)(smc + OFF_HI);
    int* swi = (int*)(smc + OFF_WI);
    float* sdx = (float*)(smc + OFF_DX);
    float* sdy = (float*)(smc + OFF_DY);

    const int t = threadIdx.x, lane = t & 31, wid = t >> 5;
    const int r0 = wid * 16;
    const int e0 = blockIdx.x * TILE;

    if (t < TILE) {
        const int h = hi[e0 + t], w = wi[e0 + t];
        shi[t] = h;
        swi[t] = w;
        sdx[t] = actor_ctrs[2 * h] - node_ctrs[2 * w];
        sdy[t] = actor_ctrs[2 * h + 1] - node_ctrs[2 * w + 1];
    }
    __syncthreads();
    // gather sM = qc[hi] + nc[wi]
    for (int idx = t; idx < TILE * 32; idx += NTH) {
        const int e = idx >> 5, c4 = idx & 31;
        const float4 a = *(const float4*)(g_qc + (size_t)shi[e] * DD + c4 * 4);
        const float4 b = *(const float4*)(g_nc + (size_t)swi[e] * DD + c4 * 4);
        *(float4*)(sM + e * STR + c4 * 4) =
            make_float4(a.x + b.x, a.y + b.y, a.z + b.z, a.w + b.w);
    }
    // H1 = relu(dist0) -> split bf16 into A tiles
    {
        const int r = t >> 1, c0 = (t & 1) * 64;
        const float dx = sdx[r], dy = sdy[r];
#pragma unroll
        for (int gb = 0; gb < 8; gb++) {
            __nv_bfloat16 h8[8], l8[8];
#pragma unroll
            for (int j = 0; j < 8; j++) {
                const int ch = c0 + gb * 8 + j;
                const float v =
                    fmaxf(fmaf(d0W[2 * ch], dx, fmaf(d0W[2 * ch + 1], dy, d0b[ch])), 0.f);
                bf16_split(v, h8[j], l8[j]);
            }
            const int off = r * RSB + (c0 + gb * 8) * 2;
            *(uint4*)(sAh + off) = *(uint4*)h8;
            *(uint4*)(sAl + off) = *(uint4*)l8;
        }
    }
    copy_w(sWh, sWl, 0, t);
    __syncthreads();

    const uint32_t aH = sb + OFF_AH + (uint32_t)(r0 * RSB);
    const uint32_t aL = sb + OFF_AL + (uint32_t)(r0 * RSB);
    const uint32_t wH = sb + OFF_WH, wL = sb + OFF_WL;
    float acc[16][4];

    // GEMM1: dist1 + GN
    ZACC16(acc);
    wgemm(acc, aH, aL, wH, wL, lane);
    __syncthreads();
    gn_mma<false>(acc, sM, d1g, d1b, sAh, sAl, r0, lane);
    copy_w(sWh, sWl, 1, t);
    __syncthreads();

    // GEMM2: ctx0 (d part) + sM + GN
    ZACC16(acc);
    wgemm(acc, aH, aL, wH, wL, lane);
    __syncthreads();
    gn_mma<true>(acc, sM, c0g, c0b, sAh, sAl, r0, lane);
    copy_w(sWh, sWl, 2, t);
    __syncthreads();

    // GEMM3: ctx1 -> scatter
    ZACC16(acc);
    wgemm(acc, aH, aL, wH, wL, lane);
    {
        const int rlo = r0 + (lane >> 2), rhi = rlo + 8;
        const int cb = 2 * (lane & 3);
        const float* plo = g_a + (size_t)shi[rlo] * DD;
        const float* phi = g_a + (size_t)shi[rhi] * DD;
#pragma unroll
        for (int nt = 0; nt < 16; nt++) {
            const int col = nt * 8 + cb;
            redv2(plo + col, acc[nt][0], acc[nt][1]);
            redv2(phi + col, acc[nt][2], acc[nt][3]);
        }
    }
}

#define SMEM_PRE ((2 * TILE * STR + 2 * SWBUF + TILE * 4) * 4)
#define SMEM_NODE ((TILE * STR + 2 * SWBUF) * 4)
#define SMEM_POST ((TILE * STR + 2 * SWBUF + TILE * 4) * 4)

extern "C" void kernel_launch(void* const* d_in, const int* in_sizes, int n_in,
                              void* d_out, int out_size) {
    (void)in_sizes; (void)n_in; (void)out_size;
    const float* actors = (const float*)d_in[0];
    const float* nodes = (const float*)d_in[1];
    const float* actor_ctrs = (const float*)d_in[2];
    const float* node_ctrs = (const float*)d_in[3];
    const int* hi = (const int*)d_in[4];
    const int* wi = (const int*)d_in[5];
    const float* d0W = (const float*)d_in[6];
    const float* d0b = (const float*)d_in[7];
    const float* d1W = (const float*)d_in[8];
    const float* d1g = (const float*)d_in[9];
    const float* d1b = (const float*)d_in[10];
    const float* qW = (const float*)d_in[11];
    const float* qg = (const float*)d_in[12];
    const float* qb = (const float*)d_in[13];
    const float* c0W = (const float*)d_in[14];
    const float* c0g = (const float*)d_in[15];
    const float* c0b = (const float*)d_in[16];
    const float* c1W = (const float*)d_in[17];
    const float* aW = (const float*)d_in[18];
    const float* ng = (const float*)d_in[19];
    const float* nb = (const float*)d_in[20];
    const float* lW = (const float*)d_in[21];
    const float* lg = (const float*)d_in[22];
    const float* lb = (const float*)d_in[23];
    float* out = (float*)d_out;

    cudaFuncSetAttribute(pre_kernel, cudaFuncAttributeMaxDynamicSharedMemorySize, SMEM_PRE);
    cudaFuncSetAttribute(node_kernel, cudaFuncAttributeMaxDynamicSharedMemorySize, SMEM_NODE);
    cudaFuncSetAttribute(edge_kernel, cudaFuncAttributeMaxDynamicSharedMemorySize, SMEM_EDGE);
    cudaFuncSetAttribute(post_kernel, cudaFuncAttributeMaxDynamicSharedMemorySize, SMEM_POST);

    for (int blk = 0; blk < 2; blk++) {
        const int off = blk * DD;
        const float* c0Wb = c0W + (size_t)blk * DD * 3 * DD;
        wprep_kernel<<<192, 256>>>(d1W + (size_t)blk * DD * DD, c0Wb,
                                   c1W + (size_t)blk * DD * DD);
        node_kernel<<<NN / TILE, NTH, SMEM_NODE>>>(nodes, c0Wb + 2 * DD);
        pre_kernel<<<NA / TILE, NTH, SMEM_PRE>>>(actors, qW + (size_t)blk * DD * DD, qg + off,
                                                 qb + off, c0Wb + DD, aW + (size_t)blk * DD * DD,
                                                 blk);
        edge_kernel<<<NE / TILE, NTH, SMEM_EDGE>>>(actor_ctrs, node_ctrs, hi, wi,
                                                   d0W + (size_t)blk * DD * 2, d0b + off,
                                                   d1g + off, d1b + off, c0g + off, c0b + off);
        post_kernel<<<NA / TILE, NTH, SMEM_POST>>>(actors, ng + off, nb + off,
                                                   lW + (size_t)blk * DD * DD, lg + off, lb + off,
                                                   out, blk);
    }
}